// round 15
// baseline (speedup 1.0000x reference)
#include <cuda_runtime.h>
#include <cuda_fp16.h>
#include <cstdint>

// GraphSAGE 2-layer, CSR-pull aggregation, fp16 everything-gathered,
// fp16 m16n8k16 tensor-core GEMMs, agg2 fused into GEMM2.  7 kernel nodes.
//   p1(fp16) = x @ W_l1^T, q1(fp32) = x @ W_r1^T   (GEMM1 fp16 TC)
//   CSR build: hist -> scan1 -> scan23 (zeroes cnt for next replay) -> fill
//   agg1: h(fp16) = relu( (sum p1[src]) / max(deg,1) + b1 + q1 )  [fp32 accum]
//   GEMM2 (fused): per-block pre-phase gathers s2 rows for its own tile,
//                  then out = [s2/deg | h] @ [W_l2 | W_r2]^T + b2
//
// deg = g_cursor - g_starts (cursor == segment end after fill).
// __device__ globals referenced ONLY inside kernels.

#define NMAX 100000
#define EMAX 1600000

__device__ __align__(16) __half2 g_p1h [(size_t)NMAX * 32];
__device__ __align__(16) float   g_q1  [(size_t)NMAX * 64];
__device__ __align__(16) __half2 g_hh  [(size_t)NMAX * 32];
__device__ __align__(16) float   g_s2  [(size_t)NMAX * 64];
__device__ __align__(16) int   g_cnt   [NMAX];
__device__ __align__(16) int   g_starts[NMAX];
__device__ __align__(16) int   g_cursor[NMAX];
__device__ __align__(16) int   g_bsum  [256];
__device__ __align__(16) int   g_csrc  [EMAX];

// ---------------------------------------------------------------------------
// CSR build
// ---------------------------------------------------------------------------
__global__ void hist_kernel(const int* __restrict__ ei, int E) {
    int e = blockIdx.x * 256 + threadIdx.x;
    if (e < E) atomicAdd(&g_cnt[__ldg(ei + E + e)], 1);
}

__global__ void scan1_kernel(int N) {
    __shared__ int sm[512];
    int tid = threadIdx.x;
    int gid = blockIdx.x * 512 + tid;
    int v = (gid < N) ? g_cnt[gid] : 0;
    sm[tid] = v;
    __syncthreads();
#pragma unroll
    for (int off = 1; off < 512; off <<= 1) {
        int t = (tid >= off) ? sm[tid - off] : 0;
        __syncthreads();
        sm[tid] += t;
        __syncthreads();
    }
    if (gid < N) g_starts[gid] = sm[tid] - v;
    if (tid == 511) g_bsum[blockIdx.x] = sm[511];
}

// scan23: redundant per-block scan of block sums; applies offsets, inits
// cursor, and zeroes g_cnt (already consumed by scan1) for the next replay.
__global__ void scan23_kernel(int N, int nb) {
    __shared__ int sm[256];
    int tid = threadIdx.x;
    int v = (tid < nb) ? g_bsum[tid] : 0;
    sm[tid] = v;
    __syncthreads();
#pragma unroll
    for (int off = 1; off < 256; off <<= 1) {
        int t = (tid >= off) ? sm[tid - off] : 0;
        __syncthreads();
        sm[tid] += t;
        __syncthreads();
    }
    sm[tid] -= v;            // exclusive
    __syncthreads();
    int gid = blockIdx.x * 256 + tid;
    if (gid < N) {
        int s = g_starts[gid] + sm[gid >> 9];
        g_starts[gid] = s;
        g_cursor[gid] = s;
        g_cnt[gid] = 0;      // ready for next call's hist
    }
}

__global__ void fill_kernel(const int* __restrict__ ei, int E) {
    int e = blockIdx.x * 256 + threadIdx.x;
    if (e < E) {
        int s = __ldg(ei + e);
        int d = __ldg(ei + E + e);
        int slot = atomicAdd(&g_cursor[d], 1);
        g_csrc[slot] = s;
    }
}

// ---------------------------------------------------------------------------
// agg1: one warp per dst node; lane holds dims (2*lane, 2*lane+1).
// fp16 gathers from g_p1h, fp32 accumulation, x4 unroll.
// h = relu(acc*r + b1 + q1) stored fp16 (g_hh).
// ---------------------------------------------------------------------------
__global__ void agg1_kernel(const float* __restrict__ b1, int N) {
    int w = (blockIdx.x * 256 + threadIdx.x) >> 5;
    if (w >= N) return;
    int lane = threadIdx.x & 31;
    int beg = g_starts[w];
    int end = g_cursor[w];          // segment end after fill
    float2 acc = make_float2(0.f, 0.f);
    int j = beg;
    for (; j + 4 <= end; j += 4) {
        int s0 = __ldg(g_csrc + j);
        int s1 = __ldg(g_csrc + j + 1);
        int s2 = __ldg(g_csrc + j + 2);
        int s3 = __ldg(g_csrc + j + 3);
        float2 a = __half22float2(__ldg(g_p1h + (size_t)s0 * 32 + lane));
        float2 b = __half22float2(__ldg(g_p1h + (size_t)s1 * 32 + lane));
        float2 c = __half22float2(__ldg(g_p1h + (size_t)s2 * 32 + lane));
        float2 d = __half22float2(__ldg(g_p1h + (size_t)s3 * 32 + lane));
        acc.x += (a.x + b.x) + (c.x + d.x);
        acc.y += (a.y + b.y) + (c.y + d.y);
    }
    for (; j < end; j++) {
        int s0 = __ldg(g_csrc + j);
        float2 a = __half22float2(__ldg(g_p1h + (size_t)s0 * 32 + lane));
        acc.x += a.x;
        acc.y += a.y;
    }
    float r = 1.0f / fmaxf((float)(end - beg), 1.0f);
    float2 qv = *reinterpret_cast<const float2*>(g_q1 + (size_t)w * 64 + lane * 2);
    float2 bv = *reinterpret_cast<const float2*>(b1 + lane * 2);
    float2 hv;
    hv.x = fmaxf(acc.x * r + bv.x + qv.x, 0.f);
    hv.y = fmaxf(acc.y * r + bv.y + qv.y, 0.f);
    g_hh[(size_t)w * 32 + lane] = __float22half2_rn(hv);
}

// ---------------------------------------------------------------------------
// fp16 tensor-core GEMM (m16n8k16), register-double-buffered k-chunk pipeline.
// Block: 256 threads (8 warps, 4x2), tile 128x128, K chunked by 32 halves.
// Paired-word layout: koff(w) -> fragment words adjacent => one LDS.64 each.
// LDW = 24 words/row; smem 24 KB total; 2 blocks/SM.
// MODE 1: A = x; B rows: n<64 -> Wl1, else Wr1; writes g_p1h(fp16)/g_q1(fp32)
// MODE 2: FUSED agg2 pre-phase (gather s2 for this block's 128 rows from
//         g_hh via CSR), then A cols 0..63 = s2/deg, 64..127 = h; +bias.
// ---------------------------------------------------------------------------
#define LDW 24

__device__ __forceinline__ int koff(int w) {
    return (w & ~7) + ((w & 3) << 1) + ((w >> 2) & 1);
}
__device__ __forceinline__ uint32_t packh2(float a, float b) {
    __half2 h = __floats2half2_rn(a, b);
    return *reinterpret_cast<uint32_t*>(&h);
}

#define MMA16(c, a, b) asm volatile( \
  "mma.sync.aligned.m16n8k16.row.col.f32.f16.f16.f32 " \
  "{%0,%1,%2,%3},{%4,%5,%6,%7},{%8,%9},{%0,%1,%2,%3};" \
  : "+f"(c[0]), "+f"(c[1]), "+f"(c[2]), "+f"(c[3]) \
  : "r"(a[0]), "r"(a[1]), "r"(a[2]), "r"(a[3]), "r"(b.x), "r"(b.y))

template<int MODE>
__global__ __launch_bounds__(256, 2) void gemm_tc(
    const float* __restrict__ x,
    const float* __restrict__ Wl, const float* __restrict__ Wr,
    const float* __restrict__ bias, float* __restrict__ outp, int N)
{
    __shared__ uint32_t As[128 * LDW];
    __shared__ uint32_t Bs[128 * LDW];
    const int tid  = threadIdx.x;
    const int m0   = blockIdx.x * 128;
    const int lane = tid & 31, warp = tid >> 5;
    const int g    = lane >> 2, t = lane & 3;
    const int rm   = (warp >> 1) * 32;
    const int cn   = (warp & 1) * 64;

    if (MODE == 2) {
        // ---- fused agg2 pre-phase: gather s2 for rows m0..m0+127 ----
        // warp handles 16 consecutive rows; same loop shape as agg1.
#pragma unroll 1
        for (int rr = 0; rr < 16; rr++) {
            int row = m0 + warp * 16 + rr;
            if (row >= N) break;
            int beg = g_starts[row];
            int end = g_cursor[row];
            float2 acc = make_float2(0.f, 0.f);
            int j = beg;
            for (; j + 4 <= end; j += 4) {
                int s0 = __ldg(g_csrc + j);
                int s1 = __ldg(g_csrc + j + 1);
                int s2 = __ldg(g_csrc + j + 2);
                int s3 = __ldg(g_csrc + j + 3);
                float2 a = __half22float2(__ldg(g_hh + (size_t)s0 * 32 + lane));
                float2 b = __half22float2(__ldg(g_hh + (size_t)s1 * 32 + lane));
                float2 c = __half22float2(__ldg(g_hh + (size_t)s2 * 32 + lane));
                float2 d = __half22float2(__ldg(g_hh + (size_t)s3 * 32 + lane));
                acc.x += (a.x + b.x) + (c.x + d.x);
                acc.y += (a.y + b.y) + (c.y + d.y);
            }
            for (; j < end; j++) {
                int s0 = __ldg(g_csrc + j);
                float2 a = __half22float2(__ldg(g_hh + (size_t)s0 * 32 + lane));
                acc.x += a.x;
                acc.y += a.y;
            }
            *reinterpret_cast<float2*>(g_s2 + (size_t)row * 64 + lane * 2) = acc;
        }
        __syncthreads();   // orders the block's g_s2 writes before loadA reads
    }

    uint2 va[4], vb[4];

    auto loadA = [&](int kc) {
#pragma unroll
        for (int it = 0; it < 4; it++) {
            int f = tid + it * 256;
            int row = f >> 3, q = f & 7;       // q: float4 index (4 k each)
            int gm = m0 + row;
            uint2 w = make_uint2(0u, 0u);
            if (gm < N) {
                if (MODE == 1) {
                    float4 v = *reinterpret_cast<const float4*>(x + (size_t)gm * 128 + kc + q * 4);
                    w.x = packh2(v.x, v.y);
                    w.y = packh2(v.z, v.w);
                } else {
                    if (kc < 64) {
                        float4 v = *reinterpret_cast<const float4*>(g_s2 + (size_t)gm * 64 + kc + q * 4);
                        int deg = g_cursor[gm] - g_starts[gm];
                        float r = 1.0f / fmaxf((float)deg, 1.0f);
                        w.x = packh2(v.x * r, v.y * r);
                        w.y = packh2(v.z * r, v.w * r);
                    } else {
                        size_t idx = (size_t)gm * 32 + ((kc - 64) >> 1) + q * 2;
                        w = __ldg(reinterpret_cast<const uint2*>(g_hh + idx));
                    }
                }
            }
            va[it] = w;
        }
    };
    auto loadB = [&](int kc) {
#pragma unroll
        for (int it = 0; it < 4; it++) {
            int f = tid + it * 256;
            int n = f >> 3, q = f & 7;
            const float* src;
            if (MODE == 1)
                src = (n < 64) ? (Wl + (size_t)n * 128 + kc + q * 4)
                               : (Wr + (size_t)(n - 64) * 128 + kc + q * 4);
            else
                src = ((kc < 64) ? (Wl + (size_t)n * 64 + kc)
                                 : (Wr + (size_t)n * 64 + (kc - 64))) + q * 4;
            float4 v = *reinterpret_cast<const float4*>(src);
            vb[it] = make_uint2(packh2(v.x, v.y), packh2(v.z, v.w));
        }
    };

    float acc[2][8][4];
#pragma unroll
    for (int i = 0; i < 2; i++)
#pragma unroll
        for (int j = 0; j < 8; j++)
#pragma unroll
            for (int q = 0; q < 4; q++) acc[i][j][q] = 0.f;

    loadA(0); loadB(0);

#pragma unroll
    for (int kc = 0; kc < 128; kc += 32) {
#pragma unroll
        for (int it = 0; it < 4; it++) {
            int f = tid + it * 256;
            int row = f >> 3, q = f & 7;
            int w0 = koff(2 * q), w1 = koff(2 * q + 1);
            As[row * LDW + w0] = va[it].x;
            As[row * LDW + w1] = va[it].y;
            Bs[row * LDW + w0] = vb[it].x;
            Bs[row * LDW + w1] = vb[it].y;
        }
        __syncthreads();
        if (kc < 96) { loadA(kc + 32); loadB(kc + 32); }
#pragma unroll
        for (int s = 0; s < 2; s++) {
            uint32_t a[2][4];
            int base = s * 8 + 2 * t;
#pragma unroll
            for (int mt = 0; mt < 2; mt++) {
                int m = rm + mt * 16 + g;
                uint2 lo = *reinterpret_cast<const uint2*>(As + m * LDW + base);
                uint2 hi = *reinterpret_cast<const uint2*>(As + (m + 8) * LDW + base);
                a[mt][0] = lo.x; a[mt][1] = hi.x; a[mt][2] = lo.y; a[mt][3] = hi.y;
            }
#pragma unroll
            for (int nt = 0; nt < 8; nt++) {
                uint2 b = *reinterpret_cast<const uint2*>(Bs + (cn + nt * 8 + g) * LDW + base);
                MMA16(acc[0][nt], a[0], b);
                MMA16(acc[1][nt], a[1], b);
            }
        }
        __syncthreads();
    }
    // ---- epilogue ----
#pragma unroll
    for (int mt = 0; mt < 2; mt++) {
#pragma unroll
        for (int nt = 0; nt < 8; nt++) {
            int row = m0 + rm + mt * 16 + g;
            int col = cn + nt * 8 + t * 2;
            if (MODE == 1) {
                int c64 = nt * 8 + t * 2;
                if (cn == 0) {
                    if (row < N)
                        g_p1h[(size_t)row * 32 + (c64 >> 1)] =
                            __floats2half2_rn(acc[mt][nt][0], acc[mt][nt][1]);
                    if (row + 8 < N)
                        g_p1h[(size_t)(row + 8) * 32 + (c64 >> 1)] =
                            __floats2half2_rn(acc[mt][nt][2], acc[mt][nt][3]);
                } else {
                    if (row < N)
                        *reinterpret_cast<float2*>(g_q1 + (size_t)row * 64 + c64) =
                            make_float2(acc[mt][nt][0], acc[mt][nt][1]);
                    if (row + 8 < N)
                        *reinterpret_cast<float2*>(g_q1 + (size_t)(row + 8) * 64 + c64) =
                            make_float2(acc[mt][nt][2], acc[mt][nt][3]);
                }
            } else {
                float2 bb = *reinterpret_cast<const float2*>(bias + col);
                if (row < N)
                    *reinterpret_cast<float2*>(outp + (size_t)row * 128 + col) =
                        make_float2(acc[mt][nt][0] + bb.x, acc[mt][nt][1] + bb.y);
                if (row + 8 < N)
                    *reinterpret_cast<float2*>(outp + (size_t)(row + 8) * 128 + col) =
                        make_float2(acc[mt][nt][2] + bb.x, acc[mt][nt][3] + bb.y);
            }
        }
    }
}

// ---------------------------------------------------------------------------
extern "C" void kernel_launch(void* const* d_in, const int* in_sizes, int n_in,
                              void* d_out, int out_size)
{
    const float* x   = (const float*)d_in[0];
    const int*   ei  = (const int*)  d_in[1];
    const float* Wl1 = (const float*)d_in[2];
    const float* Wr1 = (const float*)d_in[3];
    const float* b1  = (const float*)d_in[4];
    const float* Wl2 = (const float*)d_in[5];
    const float* Wr2 = (const float*)d_in[6];
    const float* b2  = (const float*)d_in[7];
    float* out = (float*)d_out;

    int N = in_sizes[0] / 128;
    int E = in_sizes[1] / 2;

    int egrid  = (E + 255) / 256;
    int ngrid  = (N + 255) / 256;
    int ggrid  = (N + 127) / 128;
    int agrid  = (N * 32 + 255) / 256;
    int nb1    = (N + 511) / 512;

    // Fork a side stream for the CSR build so it overlaps GEMM1.
    cudaStream_t s1;
    cudaEvent_t eFork, eBuild;
    cudaStreamCreateWithFlags(&s1, cudaStreamNonBlocking);
    cudaEventCreateWithFlags(&eFork, cudaEventDisableTiming);
    cudaEventCreateWithFlags(&eBuild, cudaEventDisableTiming);

    cudaEventRecord(eFork, 0);
    cudaStreamWaitEvent(s1, eFork, 0);

    // side stream: CSR build (g_cnt arrives zeroed; scan23 re-zeroes it)
    hist_kernel<<<egrid, 256, 0, s1>>>(ei, E);
    scan1_kernel<<<nb1, 512, 0, s1>>>(N);
    scan23_kernel<<<ngrid, 256, 0, s1>>>(N, nb1);
    fill_kernel<<<egrid, 256, 0, s1>>>(ei, E);
    cudaEventRecord(eBuild, s1);

    // main stream: GEMM1 concurrently
    gemm_tc<1><<<ggrid, 256>>>(x, Wl1, Wr1, nullptr, nullptr, N);

    // join, then the serial tail (agg2 is fused into gemm_tc<2>)
    cudaStreamWaitEvent(0, eBuild, 0);
    agg1_kernel<<<agrid, 256>>>(b1, N);
    gemm_tc<2><<<ggrid, 256>>>(nullptr, Wl2, Wr2, b2, out, N);
}

// round 16
// speedup vs baseline: 1.2992x; 1.2992x over previous
#include <cuda_runtime.h>
#include <cuda_fp16.h>
#include <cstdint>

// GraphSAGE 2-layer, CSR-pull aggregation, fp16 gathered features,
// fp16 m16n8k16 tensor-core GEMMs, two-stream overlap: CSR build || GEMM1.
//   p1(fp16) = x @ W_l1^T, q1(fp32) = x @ W_r1^T   (GEMM1 fp16 TC)
//   CSR build: hist(x4/thread) -> scan1 -> scan23 (zeroes cnt) -> fill(x4/thread)
//   agg1: h(fp16) = relu( (sum p1[src]) / max(deg,1) + b1 + q1 )  [fp32 accum]
//   agg2: s2(fp32) = sum h[src]
//   out  = [s2/deg | h] @ [W_l2 | W_r2]^T + b2     (GEMM2 fp16 TC)
//
// deg = g_cursor - g_starts (cursor == segment end after fill).
// g_cnt zeroed by scan23 after scan1 consumed it => zero at every call start.
// __device__ globals referenced ONLY inside kernels.

#define NMAX 100000
#define EMAX 1600000

__device__ __align__(16) __half2 g_p1h [(size_t)NMAX * 32];
__device__ __align__(16) float   g_q1  [(size_t)NMAX * 64];
__device__ __align__(16) __half2 g_hh  [(size_t)NMAX * 32];
__device__ __align__(16) float   g_s2  [(size_t)NMAX * 64];
__device__ __align__(16) int   g_cnt   [NMAX];
__device__ __align__(16) int   g_starts[NMAX];
__device__ __align__(16) int   g_cursor[NMAX];
__device__ __align__(16) int   g_bsum  [256];
__device__ __align__(16) int   g_csrc  [EMAX];

// ---------------------------------------------------------------------------
// CSR build
// ---------------------------------------------------------------------------
// 4 edges per thread, int4 dst loads, 4 independent atomics (MLP=4).
__global__ void hist_kernel(const int* __restrict__ ei, int E) {
    int i = blockIdx.x * 256 + threadIdx.x;
    int base = i * 4;
    if (base + 3 < E) {
        int4 d = __ldg(reinterpret_cast<const int4*>(ei + E + base));
        atomicAdd(&g_cnt[d.x], 1);
        atomicAdd(&g_cnt[d.y], 1);
        atomicAdd(&g_cnt[d.z], 1);
        atomicAdd(&g_cnt[d.w], 1);
    } else {
        for (int e = base; e < E; e++)
            atomicAdd(&g_cnt[__ldg(ei + E + e)], 1);
    }
}

__global__ void scan1_kernel(int N) {
    __shared__ int sm[512];
    int tid = threadIdx.x;
    int gid = blockIdx.x * 512 + tid;
    int v = (gid < N) ? g_cnt[gid] : 0;
    sm[tid] = v;
    __syncthreads();
#pragma unroll
    for (int off = 1; off < 512; off <<= 1) {
        int t = (tid >= off) ? sm[tid - off] : 0;
        __syncthreads();
        sm[tid] += t;
        __syncthreads();
    }
    if (gid < N) g_starts[gid] = sm[tid] - v;
    if (tid == 511) g_bsum[blockIdx.x] = sm[511];
}

// scan23: per-block redundant scan of block sums; applies offsets, inits
// cursor, zeroes g_cnt (already consumed by scan1) for the next replay.
__global__ void scan23_kernel(int N, int nb) {
    __shared__ int sm[256];
    int tid = threadIdx.x;
    int v = (tid < nb) ? g_bsum[tid] : 0;
    sm[tid] = v;
    __syncthreads();
#pragma unroll
    for (int off = 1; off < 256; off <<= 1) {
        int t = (tid >= off) ? sm[tid - off] : 0;
        __syncthreads();
        sm[tid] += t;
        __syncthreads();
    }
    sm[tid] -= v;            // exclusive
    __syncthreads();
    int gid = blockIdx.x * 256 + tid;
    if (gid < N) {
        int s = g_starts[gid] + sm[gid >> 9];
        g_starts[gid] = s;
        g_cursor[gid] = s;
        g_cnt[gid] = 0;      // ready for next call's hist
    }
}

// 4 edges per thread, int4 src/dst loads, 4 independent atomic+store chains.
__global__ void fill_kernel(const int* __restrict__ ei, int E) {
    int i = blockIdx.x * 256 + threadIdx.x;
    int base = i * 4;
    if (base + 3 < E) {
        int4 s = __ldg(reinterpret_cast<const int4*>(ei + base));
        int4 d = __ldg(reinterpret_cast<const int4*>(ei + E + base));
        int p0 = atomicAdd(&g_cursor[d.x], 1);
        int p1 = atomicAdd(&g_cursor[d.y], 1);
        int p2 = atomicAdd(&g_cursor[d.z], 1);
        int p3 = atomicAdd(&g_cursor[d.w], 1);
        g_csrc[p0] = s.x;
        g_csrc[p1] = s.y;
        g_csrc[p2] = s.z;
        g_csrc[p3] = s.w;
    } else {
        for (int e = base; e < E; e++) {
            int s = __ldg(ei + e);
            int d = __ldg(ei + E + e);
            g_csrc[atomicAdd(&g_cursor[d], 1)] = s;
        }
    }
}

// ---------------------------------------------------------------------------
// aggregate (round-10/14 proven): one warp per dst node; lane holds dims
// (2*lane, 2*lane+1); fp16 gathers, fp32 accumulation, x4 unroll.
// LAYER 1: g_p1h -> h = relu(acc*r + b1 + q1) stored fp16 (g_hh)
// LAYER 2: g_hh  -> s2 fp32
// ---------------------------------------------------------------------------
template <int LAYER>
__global__ void agg_kernel(const float* __restrict__ b1, int N) {
    int w = (blockIdx.x * 256 + threadIdx.x) >> 5;
    if (w >= N) return;
    int lane = threadIdx.x & 31;
    int beg = g_starts[w];
    int end = g_cursor[w];          // segment end after fill
    const __half2* feat = (LAYER == 1) ? g_p1h : g_hh;
    float2 acc = make_float2(0.f, 0.f);
    int j = beg;
    for (; j + 4 <= end; j += 4) {
        int s0 = __ldg(g_csrc + j);
        int s1 = __ldg(g_csrc + j + 1);
        int s2 = __ldg(g_csrc + j + 2);
        int s3 = __ldg(g_csrc + j + 3);
        float2 a = __half22float2(__ldg(feat + (size_t)s0 * 32 + lane));
        float2 b = __half22float2(__ldg(feat + (size_t)s1 * 32 + lane));
        float2 c = __half22float2(__ldg(feat + (size_t)s2 * 32 + lane));
        float2 d = __half22float2(__ldg(feat + (size_t)s3 * 32 + lane));
        acc.x += (a.x + b.x) + (c.x + d.x);
        acc.y += (a.y + b.y) + (c.y + d.y);
    }
    for (; j < end; j++) {
        int s0 = __ldg(g_csrc + j);
        float2 a = __half22float2(__ldg(feat + (size_t)s0 * 32 + lane));
        acc.x += a.x;
        acc.y += a.y;
    }
    if (LAYER == 1) {
        float r = 1.0f / fmaxf((float)(end - beg), 1.0f);
        float2 qv = *reinterpret_cast<const float2*>(g_q1 + (size_t)w * 64 + lane * 2);
        float2 bv = *reinterpret_cast<const float2*>(b1 + lane * 2);
        float2 hv;
        hv.x = fmaxf(acc.x * r + bv.x + qv.x, 0.f);
        hv.y = fmaxf(acc.y * r + bv.y + qv.y, 0.f);
        g_hh[(size_t)w * 32 + lane] = __float22half2_rn(hv);
    } else {
        *reinterpret_cast<float2*>(g_s2 + (size_t)w * 64 + lane * 2) = acc;
    }
}

// ---------------------------------------------------------------------------
// fp16 tensor-core GEMM (m16n8k16), register-double-buffered k-chunk pipeline.
// Block: 256 threads (8 warps, 4x2), tile 128x128, K chunked by 32 halves.
// Paired-word layout: koff(w) -> fragment words adjacent => one LDS.64 each.
// LDW = 24 words/row; smem 24 KB total; 2 blocks/SM.
// ---------------------------------------------------------------------------
#define LDW 24

__device__ __forceinline__ int koff(int w) {
    return (w & ~7) + ((w & 3) << 1) + ((w >> 2) & 1);
}
__device__ __forceinline__ uint32_t packh2(float a, float b) {
    __half2 h = __floats2half2_rn(a, b);
    return *reinterpret_cast<uint32_t*>(&h);
}

#define MMA16(c, a, b) asm volatile( \
  "mma.sync.aligned.m16n8k16.row.col.f32.f16.f16.f32 " \
  "{%0,%1,%2,%3},{%4,%5,%6,%7},{%8,%9},{%0,%1,%2,%3};" \
  : "+f"(c[0]), "+f"(c[1]), "+f"(c[2]), "+f"(c[3]) \
  : "r"(a[0]), "r"(a[1]), "r"(a[2]), "r"(a[3]), "r"(b.x), "r"(b.y))

// MODE 1: A = x; B rows: n<64 -> Wl1, else Wr1; writes g_p1h(fp16)/g_q1(fp32)
// MODE 2: A cols 0..63 = s2 * (1/max(deg,1)), 64..127 = h (fp16 raw);
//         B: k<64 -> Wl2 else Wr2; +bias; writes outp
template<int MODE>
__global__ __launch_bounds__(256, 2) void gemm_tc(
    const float* __restrict__ x,
    const float* __restrict__ Wl, const float* __restrict__ Wr,
    const float* __restrict__ bias, float* __restrict__ outp, int N)
{
    __shared__ uint32_t As[128 * LDW];
    __shared__ uint32_t Bs[128 * LDW];
    const int tid  = threadIdx.x;
    const int m0   = blockIdx.x * 128;
    const int lane = tid & 31, warp = tid >> 5;
    const int g    = lane >> 2, t = lane & 3;
    const int rm   = (warp >> 1) * 32;
    const int cn   = (warp & 1) * 64;

    uint2 va[4], vb[4];

    auto loadA = [&](int kc) {
#pragma unroll
        for (int it = 0; it < 4; it++) {
            int f = tid + it * 256;
            int row = f >> 3, q = f & 7;       // q: float4 index (4 k each)
            int gm = m0 + row;
            uint2 w = make_uint2(0u, 0u);
            if (gm < N) {
                if (MODE == 1) {
                    float4 v = *reinterpret_cast<const float4*>(x + (size_t)gm * 128 + kc + q * 4);
                    w.x = packh2(v.x, v.y);
                    w.y = packh2(v.z, v.w);
                } else {
                    if (kc < 64) {
                        float4 v = *reinterpret_cast<const float4*>(g_s2 + (size_t)gm * 64 + kc + q * 4);
                        int deg = g_cursor[gm] - g_starts[gm];
                        float r = 1.0f / fmaxf((float)deg, 1.0f);
                        w.x = packh2(v.x * r, v.y * r);
                        w.y = packh2(v.z * r, v.w * r);
                    } else {
                        size_t idx = (size_t)gm * 32 + ((kc - 64) >> 1) + q * 2;
                        w = __ldg(reinterpret_cast<const uint2*>(g_hh + idx));
                    }
                }
            }
            va[it] = w;
        }
    };
    auto loadB = [&](int kc) {
#pragma unroll
        for (int it = 0; it < 4; it++) {
            int f = tid + it * 256;
            int n = f >> 3, q = f & 7;
            const float* src;
            if (MODE == 1)
                src = (n < 64) ? (Wl + (size_t)n * 128 + kc + q * 4)
                               : (Wr + (size_t)(n - 64) * 128 + kc + q * 4);
            else
                src = ((kc < 64) ? (Wl + (size_t)n * 64 + kc)
                                 : (Wr + (size_t)n * 64 + (kc - 64))) + q * 4;
            float4 v = *reinterpret_cast<const float4*>(src);
            vb[it] = make_uint2(packh2(v.x, v.y), packh2(v.z, v.w));
        }
    };

    float acc[2][8][4];
#pragma unroll
    for (int i = 0; i < 2; i++)
#pragma unroll
        for (int j = 0; j < 8; j++)
#pragma unroll
            for (int q = 0; q < 4; q++) acc[i][j][q] = 0.f;

    loadA(0); loadB(0);

#pragma unroll
    for (int kc = 0; kc < 128; kc += 32) {
#pragma unroll
        for (int it = 0; it < 4; it++) {
            int f = tid + it * 256;
            int row = f >> 3, q = f & 7;
            int w0 = koff(2 * q), w1 = koff(2 * q + 1);
            As[row * LDW + w0] = va[it].x;
            As[row * LDW + w1] = va[it].y;
            Bs[row * LDW + w0] = vb[it].x;
            Bs[row * LDW + w1] = vb[it].y;
        }
        __syncthreads();
        if (kc < 96) { loadA(kc + 32); loadB(kc + 32); }
#pragma unroll
        for (int s = 0; s < 2; s++) {
            uint32_t a[2][4];
            int base = s * 8 + 2 * t;
#pragma unroll
            for (int mt = 0; mt < 2; mt++) {
                int m = rm + mt * 16 + g;
                uint2 lo = *reinterpret_cast<const uint2*>(As + m * LDW + base);
                uint2 hi = *reinterpret_cast<const uint2*>(As + (m + 8) * LDW + base);
                a[mt][0] = lo.x; a[mt][1] = hi.x; a[mt][2] = lo.y; a[mt][3] = hi.y;
            }
#pragma unroll
            for (int nt = 0; nt < 8; nt++) {
                uint2 b = *reinterpret_cast<const uint2*>(Bs + (cn + nt * 8 + g) * LDW + base);
                MMA16(acc[0][nt], a[0], b);
                MMA16(acc[1][nt], a[1], b);
            }
        }
        __syncthreads();
    }
    // ---- epilogue ----
#pragma unroll
    for (int mt = 0; mt < 2; mt++) {
#pragma unroll
        for (int nt = 0; nt < 8; nt++) {
            int row = m0 + rm + mt * 16 + g;
            int col = cn + nt * 8 + t * 2;
            if (MODE == 1) {
                int c64 = nt * 8 + t * 2;
                if (cn == 0) {
                    if (row < N)
                        g_p1h[(size_t)row * 32 + (c64 >> 1)] =
                            __floats2half2_rn(acc[mt][nt][0], acc[mt][nt][1]);
                    if (row + 8 < N)
                        g_p1h[(size_t)(row + 8) * 32 + (c64 >> 1)] =
                            __floats2half2_rn(acc[mt][nt][2], acc[mt][nt][3]);
                } else {
                    if (row < N)
                        *reinterpret_cast<float2*>(g_q1 + (size_t)row * 64 + c64) =
                            make_float2(acc[mt][nt][0], acc[mt][nt][1]);
                    if (row + 8 < N)
                        *reinterpret_cast<float2*>(g_q1 + (size_t)(row + 8) * 64 + c64) =
                            make_float2(acc[mt][nt][2], acc[mt][nt][3]);
                }
            } else {
                float2 bb = *reinterpret_cast<const float2*>(bias + col);
                if (row < N)
                    *reinterpret_cast<float2*>(outp + (size_t)row * 128 + col) =
                        make_float2(acc[mt][nt][0] + bb.x, acc[mt][nt][1] + bb.y);
                if (row + 8 < N)
                    *reinterpret_cast<float2*>(outp + (size_t)(row + 8) * 128 + col) =
                        make_float2(acc[mt][nt][2] + bb.x, acc[mt][nt][3] + bb.y);
            }
        }
    }
}

// ---------------------------------------------------------------------------
extern "C" void kernel_launch(void* const* d_in, const int* in_sizes, int n_in,
                              void* d_out, int out_size)
{
    const float* x   = (const float*)d_in[0];
    const int*   ei  = (const int*)  d_in[1];
    const float* Wl1 = (const float*)d_in[2];
    const float* Wr1 = (const float*)d_in[3];
    const float* b1  = (const float*)d_in[4];
    const float* Wl2 = (const float*)d_in[5];
    const float* Wr2 = (const float*)d_in[6];
    const float* b2  = (const float*)d_in[7];
    float* out = (float*)d_out;

    int N = in_sizes[0] / 128;
    int E = in_sizes[1] / 2;

    int e4grid = (E / 4 + 256) / 256;      // 4 edges per thread
    int ngrid  = (N + 255) / 256;
    int ggrid  = (N + 127) / 128;
    int agrid  = (N * 32 + 255) / 256;
    int nb1    = (N + 511) / 512;

    // Fork a side stream for the CSR build so it overlaps GEMM1.
    cudaStream_t s1;
    cudaEvent_t eFork, eBuild;
    cudaStreamCreateWithFlags(&s1, cudaStreamNonBlocking);
    cudaEventCreateWithFlags(&eFork, cudaEventDisableTiming);
    cudaEventCreateWithFlags(&eBuild, cudaEventDisableTiming);

    cudaEventRecord(eFork, 0);
    cudaStreamWaitEvent(s1, eFork, 0);

    // side stream: CSR build (g_cnt arrives zeroed; scan23 re-zeroes it)
    hist_kernel<<<e4grid, 256, 0, s1>>>(ei, E);
    scan1_kernel<<<nb1, 512, 0, s1>>>(N);
    scan23_kernel<<<ngrid, 256, 0, s1>>>(N, nb1);
    fill_kernel<<<e4grid, 256, 0, s1>>>(ei, E);
    cudaEventRecord(eBuild, s1);

    // main stream: GEMM1 concurrently
    gemm_tc<1><<<ggrid, 256>>>(x, Wl1, Wr1, nullptr, nullptr, N);

    // join, then the serial tail
    cudaStreamWaitEvent(0, eBuild, 0);
    agg_kernel<1><<<agrid, 256>>>(b1, N);
    agg_kernel<2><<<agrid, 256>>>(nullptr, N);
    gemm_tc<2><<<ggrid, 256>>>(nullptr, Wl2, Wr2, b2, out, N);
}

// round 17
// speedup vs baseline: 1.3038x; 1.0036x over previous
#include <cuda_runtime.h>
#include <cuda_fp16.h>
#include <cstdint>

// GraphSAGE 2-layer, CSR-pull aggregation (4-aligned segments, int4 index
// loads), fp16 gathered features, fp16 m16n8k16 tensor-core GEMMs,
// two-stream overlap: CSR build || GEMM1.
//   p1(fp16) = x @ W_l1^T, q1(fp32) = x @ W_r1^T   (GEMM1 fp16 TC)
//   CSR build: hist(x4) -> scan1 -> scan23 (zeroes cnt) -> fill(x4)
//              (segment starts padded to x4 => 16B-aligned index loads)
//   agg1: h(fp16) = relu( (sum p1[src]) / max(deg,1) + b1 + q1 )  [fp32 accum]
//   agg2: s2(fp32) = sum h[src]
//   out  = [s2/deg | h] @ [W_l2 | W_r2]^T + b2     (GEMM2 fp16 TC)
//
// deg = g_cursor - g_starts (cursor == actual segment end after fill;
// padding slots between segments are never read).
// g_cnt zeroed by scan23 after scan1 consumed it => zero at every call start.
// __device__ globals referenced ONLY inside kernels.

#define NMAX 100000
#define CSRMAX 2000000   // E + 3*N padding headroom

__device__ __align__(16) __half2 g_p1h [(size_t)NMAX * 32];
__device__ __align__(16) float   g_q1  [(size_t)NMAX * 64];
__device__ __align__(16) __half2 g_hh  [(size_t)NMAX * 32];
__device__ __align__(16) float   g_s2  [(size_t)NMAX * 64];
__device__ __align__(16) int   g_cnt   [NMAX];
__device__ __align__(16) int   g_starts[NMAX];
__device__ __align__(16) int   g_cursor[NMAX];
__device__ __align__(16) int   g_bsum  [256];
__device__ __align__(16) int   g_csrc  [CSRMAX];

// ---------------------------------------------------------------------------
// CSR build
// ---------------------------------------------------------------------------
// 4 edges per thread, int4 dst loads, 4 independent atomics.
__global__ void hist_kernel(const int* __restrict__ ei, int E) {
    int i = blockIdx.x * 256 + threadIdx.x;
    int base = i * 4;
    if (base + 3 < E) {
        int4 d = __ldg(reinterpret_cast<const int4*>(ei + E + base));
        atomicAdd(&g_cnt[d.x], 1);
        atomicAdd(&g_cnt[d.y], 1);
        atomicAdd(&g_cnt[d.z], 1);
        atomicAdd(&g_cnt[d.w], 1);
    } else {
        for (int e = base; e < E; e++)
            atomicAdd(&g_cnt[__ldg(ei + E + e)], 1);
    }
}

// scan1 over PADDED counts ((c+3)&~3): starts become 4-aligned.
__global__ void scan1_kernel(int N) {
    __shared__ int sm[512];
    int tid = threadIdx.x;
    int gid = blockIdx.x * 512 + tid;
    int v = (gid < N) ? ((g_cnt[gid] + 3) & ~3) : 0;
    sm[tid] = v;
    __syncthreads();
#pragma unroll
    for (int off = 1; off < 512; off <<= 1) {
        int t = (tid >= off) ? sm[tid - off] : 0;
        __syncthreads();
        sm[tid] += t;
        __syncthreads();
    }
    if (gid < N) g_starts[gid] = sm[tid] - v;
    if (tid == 511) g_bsum[blockIdx.x] = sm[511];
}

// scan23: per-block redundant scan of block sums; applies offsets, inits
// cursor, zeroes g_cnt (already consumed by scan1) for the next replay.
__global__ void scan23_kernel(int N, int nb) {
    __shared__ int sm[256];
    int tid = threadIdx.x;
    int v = (tid < nb) ? g_bsum[tid] : 0;
    sm[tid] = v;
    __syncthreads();
#pragma unroll
    for (int off = 1; off < 256; off <<= 1) {
        int t = (tid >= off) ? sm[tid - off] : 0;
        __syncthreads();
        sm[tid] += t;
        __syncthreads();
    }
    sm[tid] -= v;            // exclusive
    __syncthreads();
    int gid = blockIdx.x * 256 + tid;
    if (gid < N) {
        int s = g_starts[gid] + sm[gid >> 9];
        g_starts[gid] = s;
        g_cursor[gid] = s;
        g_cnt[gid] = 0;      // ready for next call's hist
    }
}

// 4 edges per thread, int4 src/dst loads.
__global__ void fill_kernel(const int* __restrict__ ei, int E) {
    int i = blockIdx.x * 256 + threadIdx.x;
    int base = i * 4;
    if (base + 3 < E) {
        int4 s = __ldg(reinterpret_cast<const int4*>(ei + base));
        int4 d = __ldg(reinterpret_cast<const int4*>(ei + E + base));
        int p0 = atomicAdd(&g_cursor[d.x], 1);
        int p1 = atomicAdd(&g_cursor[d.y], 1);
        int p2 = atomicAdd(&g_cursor[d.z], 1);
        int p3 = atomicAdd(&g_cursor[d.w], 1);
        g_csrc[p0] = s.x;
        g_csrc[p1] = s.y;
        g_csrc[p2] = s.z;
        g_csrc[p3] = s.w;
    } else {
        for (int e = base; e < E; e++) {
            int s = __ldg(ei + e);
            int d = __ldg(ei + E + e);
            g_csrc[atomicAdd(&g_cursor[d], 1)] = s;
        }
    }
}

// ---------------------------------------------------------------------------
// aggregate: one warp per dst node; lane holds dims (2*lane, 2*lane+1).
// beg is 16B-aligned -> indices load as ONE uniform int4 per 4 edges
// (prefetched one step ahead so idx latency overlaps feature gathers).
// fp16 feature gathers, fp32 accumulation.
// LAYER 1: g_p1h -> h = relu(acc*r + b1 + q1) stored fp16 (g_hh)
// LAYER 2: g_hh  -> s2 fp32
// ---------------------------------------------------------------------------
template <int LAYER>
__global__ void agg_kernel(const float* __restrict__ b1, int N) {
    int w = (blockIdx.x * 256 + threadIdx.x) >> 5;
    if (w >= N) return;
    int lane = threadIdx.x & 31;
    int beg = g_starts[w];           // 4-aligned
    int end = g_cursor[w];           // actual segment end
    const __half2* feat = (LAYER == 1) ? g_p1h : g_hh;
    float2 acc = make_float2(0.f, 0.f);
    int j = beg;
    if (j + 4 <= end) {
        int4 s4 = __ldg(reinterpret_cast<const int4*>(g_csrc + j));
        for (; j + 8 <= end; j += 4) {
            int4 nxt = __ldg(reinterpret_cast<const int4*>(g_csrc + j + 4));
            float2 a = __half22float2(__ldg(feat + (size_t)s4.x * 32 + lane));
            float2 b = __half22float2(__ldg(feat + (size_t)s4.y * 32 + lane));
            float2 c = __half22float2(__ldg(feat + (size_t)s4.z * 32 + lane));
            float2 d = __half22float2(__ldg(feat + (size_t)s4.w * 32 + lane));
            acc.x += (a.x + b.x) + (c.x + d.x);
            acc.y += (a.y + b.y) + (c.y + d.y);
            s4 = nxt;
        }
        {
            float2 a = __half22float2(__ldg(feat + (size_t)s4.x * 32 + lane));
            float2 b = __half22float2(__ldg(feat + (size_t)s4.y * 32 + lane));
            float2 c = __half22float2(__ldg(feat + (size_t)s4.z * 32 + lane));
            float2 d = __half22float2(__ldg(feat + (size_t)s4.w * 32 + lane));
            acc.x += (a.x + b.x) + (c.x + d.x);
            acc.y += (a.y + b.y) + (c.y + d.y);
            j += 4;
        }
    }
    for (; j < end; j++) {
        int s0 = __ldg(g_csrc + j);
        float2 a = __half22float2(__ldg(feat + (size_t)s0 * 32 + lane));
        acc.x += a.x;
        acc.y += a.y;
    }
    if (LAYER == 1) {
        float r = 1.0f / fmaxf((float)(end - beg), 1.0f);
        float2 qv = *reinterpret_cast<const float2*>(g_q1 + (size_t)w * 64 + lane * 2);
        float2 bv = *reinterpret_cast<const float2*>(b1 + lane * 2);
        float2 hv;
        hv.x = fmaxf(acc.x * r + bv.x + qv.x, 0.f);
        hv.y = fmaxf(acc.y * r + bv.y + qv.y, 0.f);
        g_hh[(size_t)w * 32 + lane] = __float22half2_rn(hv);
    } else {
        *reinterpret_cast<float2*>(g_s2 + (size_t)w * 64 + lane * 2) = acc;
    }
}

// ---------------------------------------------------------------------------
// fp16 tensor-core GEMM (m16n8k16), register-double-buffered k-chunk pipeline.
// Block: 256 threads (8 warps, 4x2), tile 128x128, K chunked by 32 halves.
// Paired-word layout: koff(w) -> fragment words adjacent => one LDS.64 each.
// LDW = 24 words/row; smem 24 KB total; 2 blocks/SM.
// ---------------------------------------------------------------------------
#define LDW 24

__device__ __forceinline__ int koff(int w) {
    return (w & ~7) + ((w & 3) << 1) + ((w >> 2) & 1);
}
__device__ __forceinline__ uint32_t packh2(float a, float b) {
    __half2 h = __floats2half2_rn(a, b);
    return *reinterpret_cast<uint32_t*>(&h);
}

#define MMA16(c, a, b) asm volatile( \
  "mma.sync.aligned.m16n8k16.row.col.f32.f16.f16.f32 " \
  "{%0,%1,%2,%3},{%4,%5,%6,%7},{%8,%9},{%0,%1,%2,%3};" \
  : "+f"(c[0]), "+f"(c[1]), "+f"(c[2]), "+f"(c[3]) \
  : "r"(a[0]), "r"(a[1]), "r"(a[2]), "r"(a[3]), "r"(b.x), "r"(b.y))

// MODE 1: A = x; B rows: n<64 -> Wl1, else Wr1; writes g_p1h(fp16)/g_q1(fp32)
// MODE 2: A cols 0..63 = s2 * (1/max(deg,1)), 64..127 = h (fp16 raw);
//         B: k<64 -> Wl2 else Wr2; +bias; writes outp
template<int MODE>
__global__ __launch_bounds__(256, 2) void gemm_tc(
    const float* __restrict__ x,
    const float* __restrict__ Wl, const float* __restrict__ Wr,
    const float* __restrict__ bias, float* __restrict__ outp, int N)
{
    __shared__ uint32_t As[128 * LDW];
    __shared__ uint32_t Bs[128 * LDW];
    const int tid  = threadIdx.x;
    const int m0   = blockIdx.x * 128;
    const int lane = tid & 31, warp = tid >> 5;
    const int g    = lane >> 2, t = lane & 3;
    const int rm   = (warp >> 1) * 32;
    const int cn   = (warp & 1) * 64;

    uint2 va[4], vb[4];

    auto loadA = [&](int kc) {
#pragma unroll
        for (int it = 0; it < 4; it++) {
            int f = tid + it * 256;
            int row = f >> 3, q = f & 7;       // q: float4 index (4 k each)
            int gm = m0 + row;
            uint2 w = make_uint2(0u, 0u);
            if (gm < N) {
                if (MODE == 1) {
                    float4 v = *reinterpret_cast<const float4*>(x + (size_t)gm * 128 + kc + q * 4);
                    w.x = packh2(v.x, v.y);
                    w.y = packh2(v.z, v.w);
                } else {
                    if (kc < 64) {
                        float4 v = *reinterpret_cast<const float4*>(g_s2 + (size_t)gm * 64 + kc + q * 4);
                        int deg = g_cursor[gm] - g_starts[gm];
                        float r = 1.0f / fmaxf((float)deg, 1.0f);
                        w.x = packh2(v.x * r, v.y * r);
                        w.y = packh2(v.z * r, v.w * r);
                    } else {
                        size_t idx = (size_t)gm * 32 + ((kc - 64) >> 1) + q * 2;
                        w = __ldg(reinterpret_cast<const uint2*>(g_hh + idx));
                    }
                }
            }
            va[it] = w;
        }
    };
    auto loadB = [&](int kc) {
#pragma unroll
        for (int it = 0; it < 4; it++) {
            int f = tid + it * 256;
            int n = f >> 3, q = f & 7;
            const float* src;
            if (MODE == 1)
                src = (n < 64) ? (Wl + (size_t)n * 128 + kc + q * 4)
                               : (Wr + (size_t)(n - 64) * 128 + kc + q * 4);
            else
                src = ((kc < 64) ? (Wl + (size_t)n * 64 + kc)
                                 : (Wr + (size_t)n * 64 + (kc - 64))) + q * 4;
            float4 v = *reinterpret_cast<const float4*>(src);
            vb[it] = make_uint2(packh2(v.x, v.y), packh2(v.z, v.w));
        }
    };

    float acc[2][8][4];
#pragma unroll
    for (int i = 0; i < 2; i++)
#pragma unroll
        for (int j = 0; j < 8; j++)
#pragma unroll
            for (int q = 0; q < 4; q++) acc[i][j][q] = 0.f;

    loadA(0); loadB(0);

#pragma unroll
    for (int kc = 0; kc < 128; kc += 32) {
#pragma unroll
        for (int it = 0; it < 4; it++) {
            int f = tid + it * 256;
            int row = f >> 3, q = f & 7;
            int w0 = koff(2 * q), w1 = koff(2 * q + 1);
            As[row * LDW + w0] = va[it].x;
            As[row * LDW + w1] = va[it].y;
            Bs[row * LDW + w0] = vb[it].x;
            Bs[row * LDW + w1] = vb[it].y;
        }
        __syncthreads();
        if (kc < 96) { loadA(kc + 32); loadB(kc + 32); }
#pragma unroll
        for (int s = 0; s < 2; s++) {
            uint32_t a[2][4];
            int base = s * 8 + 2 * t;
#pragma unroll
            for (int mt = 0; mt < 2; mt++) {
                int m = rm + mt * 16 + g;
                uint2 lo = *reinterpret_cast<const uint2*>(As + m * LDW + base);
                uint2 hi = *reinterpret_cast<const uint2*>(As + (m + 8) * LDW + base);
                a[mt][0] = lo.x; a[mt][1] = hi.x; a[mt][2] = lo.y; a[mt][3] = hi.y;
            }
#pragma unroll
            for (int nt = 0; nt < 8; nt++) {
                uint2 b = *reinterpret_cast<const uint2*>(Bs + (cn + nt * 8 + g) * LDW + base);
                MMA16(acc[0][nt], a[0], b);
                MMA16(acc[1][nt], a[1], b);
            }
        }
        __syncthreads();
    }
    // ---- epilogue ----
#pragma unroll
    for (int mt = 0; mt < 2; mt++) {
#pragma unroll
        for (int nt = 0; nt < 8; nt++) {
            int row = m0 + rm + mt * 16 + g;
            int col = cn + nt * 8 + t * 2;
            if (MODE == 1) {
                int c64 = nt * 8 + t * 2;
                if (cn == 0) {
                    if (row < N)
                        g_p1h[(size_t)row * 32 + (c64 >> 1)] =
                            __floats2half2_rn(acc[mt][nt][0], acc[mt][nt][1]);
                    if (row + 8 < N)
                        g_p1h[(size_t)(row + 8) * 32 + (c64 >> 1)] =
                            __floats2half2_rn(acc[mt][nt][2], acc[mt][nt][3]);
                } else {
                    if (row < N)
                        *reinterpret_cast<float2*>(g_q1 + (size_t)row * 64 + c64) =
                            make_float2(acc[mt][nt][0], acc[mt][nt][1]);
                    if (row + 8 < N)
                        *reinterpret_cast<float2*>(g_q1 + (size_t)(row + 8) * 64 + c64) =
                            make_float2(acc[mt][nt][2], acc[mt][nt][3]);
                }
            } else {
                float2 bb = *reinterpret_cast<const float2*>(bias + col);
                if (row < N)
                    *reinterpret_cast<float2*>(outp + (size_t)row * 128 + col) =
                        make_float2(acc[mt][nt][0] + bb.x, acc[mt][nt][1] + bb.y);
                if (row + 8 < N)
                    *reinterpret_cast<float2*>(outp + (size_t)(row + 8) * 128 + col) =
                        make_float2(acc[mt][nt][2] + bb.x, acc[mt][nt][3] + bb.y);
            }
        }
    }
}

// ---------------------------------------------------------------------------
extern "C" void kernel_launch(void* const* d_in, const int* in_sizes, int n_in,
                              void* d_out, int out_size)
{
    const float* x   = (const float*)d_in[0];
    const int*   ei  = (const int*)  d_in[1];
    const float* Wl1 = (const float*)d_in[2];
    const float* Wr1 = (const float*)d_in[3];
    const float* b1  = (const float*)d_in[4];
    const float* Wl2 = (const float*)d_in[5];
    const float* Wr2 = (const float*)d_in[6];
    const float* b2  = (const float*)d_in[7];
    float* out = (float*)d_out;

    int N = in_sizes[0] / 128;
    int E = in_sizes[1] / 2;

    int e4grid = (E / 4 + 256) / 256;      // 4 edges per thread
    int ngrid  = (N + 255) / 256;
    int ggrid  = (N + 127) / 128;
    int agrid  = (N * 32 + 255) / 256;
    int nb1    = (N + 511) / 512;

    // Fork a side stream for the CSR build so it overlaps GEMM1.
    cudaStream_t s1;
    cudaEvent_t eFork, eBuild;
    cudaStreamCreateWithFlags(&s1, cudaStreamNonBlocking);
    cudaEventCreateWithFlags(&eFork, cudaEventDisableTiming);
    cudaEventCreateWithFlags(&eBuild, cudaEventDisableTiming);

    cudaEventRecord(eFork, 0);
    cudaStreamWaitEvent(s1, eFork, 0);

    // side stream: CSR build (g_cnt arrives zeroed; scan23 re-zeroes it)
    hist_kernel<<<e4grid, 256, 0, s1>>>(ei, E);
    scan1_kernel<<<nb1, 512, 0, s1>>>(N);
    scan23_kernel<<<ngrid, 256, 0, s1>>>(N, nb1);
    fill_kernel<<<e4grid, 256, 0, s1>>>(ei, E);
    cudaEventRecord(eBuild, s1);

    // main stream: GEMM1 concurrently
    gemm_tc<1><<<ggrid, 256>>>(x, Wl1, Wr1, nullptr, nullptr, N);

    // join, then the serial tail
    cudaStreamWaitEvent(0, eBuild, 0);
    agg_kernel<1><<<agrid, 256>>>(b1, N);
    agg_kernel<2><<<agrid, 256>>>(nullptr, N);
    gemm_tc<2><<<ggrid, 256>>>(nullptr, Wl2, Wr2, b2, out, N);
}